// round 11
// baseline (speedup 1.0000x reference)
#include <cuda_runtime.h>
#include <cuda_bf16.h>
#include <cooperative_groups.h>
#include <cstdint>
#include <cstddef>

namespace cg = cooperative_groups;
using u64 = unsigned long long;

#define BATCH 128
#define TLEN  1024
#define HID   256
#define G4    1024  // 4*HID

// ---------------- packed f32x2 helpers ----------------
__device__ __forceinline__ u64 ffma2(u64 a, u64 b, u64 c) {
    u64 d;
    asm("fma.rn.f32x2 %0, %1, %2, %3;" : "=l"(d) : "l"(a), "l"(b), "l"(c));
    return d;
}
__device__ __forceinline__ u64 pack2(float lo, float hi) {
    u64 r;
    asm("mov.b64 %0, {%1, %2};" : "=l"(r) : "f"(lo), "f"(hi));
    return r;
}
__device__ __forceinline__ float f2lo(u64 v) { return __uint_as_float((unsigned)(v & 0xffffffffull)); }
__device__ __forceinline__ float f2hi(u64 v) { return __uint_as_float((unsigned)(v >> 32)); }

__device__ __forceinline__ float sigm_f(float x) {
    x = fminf(fmaxf(x, -30.f), 30.f);
    return __fdividef(1.f, 1.f + __expf(-x));
}
__device__ __forceinline__ float tanh_f(float x) {
    x = fminf(fmaxf(x, -15.f), 15.f);
    float e = __expf(2.f * x);
    return __fdividef(e - 1.f, e + 1.f);
}

// ---------------- cluster async-store primitives ----------------
__device__ __forceinline__ unsigned smem_u32(const void* p) {
    return (unsigned)__cvta_generic_to_shared(p);
}
__device__ __forceinline__ unsigned mapa_u32(unsigned laddr, unsigned rank) {
    unsigned r;
    asm("mapa.shared::cluster.u32 %0, %1, %2;" : "=r"(r) : "r"(laddr), "r"(rank));
    return r;
}
__device__ __forceinline__ void st_async_f32(unsigned raddr, float v, unsigned rmbar) {
    asm volatile("st.async.shared::cluster.mbarrier::complete_tx::bytes.b32 [%0], %1, [%2];"
                 :: "r"(raddr), "r"(__float_as_uint(v)), "r"(rmbar) : "memory");
}
__device__ __forceinline__ void mbar_init(unsigned mbar, unsigned cnt) {
    asm volatile("mbarrier.init.shared.b64 [%0], %1;" :: "r"(mbar), "r"(cnt) : "memory");
}
__device__ __forceinline__ void mbar_expect_tx(unsigned mbar, unsigned bytes) {
    asm volatile("mbarrier.arrive.expect_tx.shared.b64 _, [%0], %1;"
                 :: "r"(mbar), "r"(bytes) : "memory");
}
__device__ __forceinline__ void mbar_wait_cluster(unsigned mbar, unsigned parity) {
    asm volatile(
        "{\n\t"
        ".reg .pred P;\n"
        "LWAIT_%=:\n\t"
        "mbarrier.try_wait.parity.acquire.cluster.shared::cta.b64 P, [%0], %1, 0x989680;\n\t"
        "@P bra LDONE_%=;\n\t"
        "bra LWAIT_%=;\n"
        "LDONE_%=:\n\t"
        "}"
        :: "r"(mbar), "r"(parity) : "memory");
}
__device__ __forceinline__ void named_bar_sync(int id, int cnt) {
    asm volatile("bar.sync %0, %1;" :: "r"(id), "r"(cnt) : "memory");
}
__device__ __forceinline__ void named_bar_arrive(int id, int cnt) {
    asm volatile("bar.arrive %0, %1;" :: "r"(id), "r"(cnt) : "memory");
}

// ---------------- scratch (static device globals) ----------------
__device__ float g_xw[(size_t)BATCH * TLEN * G4];     // 512 MB, reused by both layers
__device__ float g_hseq[(size_t)BATCH * TLEN * HID];  // 128 MB
__device__ float g_hlast[BATCH * HID];

// ---------------------------------------------------------------------------
// GEMM: C[M,1024] = A[M,K] @ B[K,1024] + bias, M=131072, K in {128,256}
// 128x128 tile, BK=16, 256 threads, 8x8 micro-tile, FFMA2, double-buffered.
// ---------------------------------------------------------------------------
__global__ __launch_bounds__(256, 2)
void gemm_bias_kernel(const float* __restrict__ A, const float* __restrict__ B,
                      const float* __restrict__ bias, float* __restrict__ C, int K)
{
    const int N = G4;
    __shared__ float As[2][16][128];
    __shared__ float Bs[2][16][128];

    const int tid = threadIdx.x;
    const int n0  = blockIdx.x * 128;
    const size_t m0 = (size_t)blockIdx.y * 128;
    const int tn = tid & 15;
    const int tm = tid >> 4;

    float4 av[2], bv[2];
    const int NKB = K >> 4;

    auto ldg_tiles = [&](int k0) {
#pragma unroll
        for (int i = 0; i < 2; i++) {
            int idx = tid + i * 256;
            int ar = idx >> 2, kq = idx & 3;
            av[i] = *(const float4*)&A[(m0 + ar) * K + k0 + kq * 4];
            int kr = idx >> 5, nq = idx & 31;
            bv[i] = *(const float4*)&B[(size_t)(k0 + kr) * N + n0 + nq * 4];
        }
    };
    auto sts_tiles = [&](int buf) {
#pragma unroll
        for (int i = 0; i < 2; i++) {
            int idx = tid + i * 256;
            int ar = idx >> 2, kq = idx & 3;
            As[buf][kq * 4 + 0][ar] = av[i].x;
            As[buf][kq * 4 + 1][ar] = av[i].y;
            As[buf][kq * 4 + 2][ar] = av[i].z;
            As[buf][kq * 4 + 3][ar] = av[i].w;
            int kr = idx >> 5, nq = idx & 31;
            *(float4*)&Bs[buf][kr][nq * 4] = bv[i];
        }
    };

    u64 acc[8][4];
#pragma unroll
    for (int m = 0; m < 8; m++)
#pragma unroll
        for (int j = 0; j < 4; j++) acc[m][j] = 0ull;

    ldg_tiles(0);
    sts_tiles(0);
    __syncthreads();

    for (int kb = 0; kb < NKB; kb++) {
        if (kb + 1 < NKB) ldg_tiles((kb + 1) << 4);
        const int buf = kb & 1;
#pragma unroll
        for (int k = 0; k < 16; k++) {
            float4 a0 = *(const float4*)&As[buf][k][tm * 8];
            float4 a1 = *(const float4*)&As[buf][k][tm * 8 + 4];
            u64 b0v = *(const u64*)&Bs[buf][k][2 * tn];
            u64 b1v = *(const u64*)&Bs[buf][k][2 * tn + 32];
            u64 b2v = *(const u64*)&Bs[buf][k][2 * tn + 64];
            u64 b3v = *(const u64*)&Bs[buf][k][2 * tn + 96];
            float aa[8] = {a0.x, a0.y, a0.z, a0.w, a1.x, a1.y, a1.z, a1.w};
#pragma unroll
            for (int m = 0; m < 8; m++) {
                u64 am = pack2(aa[m], aa[m]);
                acc[m][0] = ffma2(am, b0v, acc[m][0]);
                acc[m][1] = ffma2(am, b1v, acc[m][1]);
                acc[m][2] = ffma2(am, b2v, acc[m][2]);
                acc[m][3] = ffma2(am, b3v, acc[m][3]);
            }
        }
        if (kb + 1 < NKB) sts_tiles(buf ^ 1);
        __syncthreads();
    }

    float bias_r[8];
#pragma unroll
    for (int j = 0; j < 4; j++) {
        bias_r[2 * j]     = bias[n0 + 2 * tn + 32 * j];
        bias_r[2 * j + 1] = bias[n0 + 2 * tn + 32 * j + 1];
    }

#pragma unroll
    for (int m = 0; m < 8; m++) {
        size_t row = m0 + tm * 8 + m;
        float* cp = &C[row * N + n0];
#pragma unroll
        for (int j = 0; j < 4; j++) {
            float2 v;
            v.x = f2lo(acc[m][j]) + bias_r[2 * j];
            v.y = f2hi(acc[m][j]) + bias_r[2 * j + 1];
            *(float2*)&cp[2 * tn + 32 * j] = v;
        }
    }
}

// ---------------------------------------------------------------------------
// Persistent-cluster LSTM recurrence — FOUR-GROUP pipeline (2 rows/group),
// 256 threads (R7 champion thread layout), st.async exchange, xw prefetch
// double-buffered one full step ahead.
// Grid: 128 CTAs = 16 clusters x 8 CTAs.
// Thread phase-1 role: gcA = tid&63, gcB = gcA+64 (2 cols), kh = tid>>6
// (64-k slice) — identical mix to the champion, accumulators split 4-ways.
// Group g rows = {2g, 2g+1}; its exchange latency hides under the other 3
// groups' phase1 (~3x bigger window than the 2-group champion).
// mbars[buf*4+g], expect 2048 B each. Named barrier id 1+g, count 256;
// producers bar.arrive, the group's 2 epilogue warps bar.sync.
// ---------------------------------------------------------------------------
template <bool WRITE_SEQ>
__global__ void __cluster_dims__(8, 1, 1) __launch_bounds__(256, 1)
lstm_layer(const float* __restrict__ xw, const float* __restrict__ U,
           float* __restrict__ out_seq, float* __restrict__ out_last)
{
    __shared__ __align__(16) float hbuf[2][8][HID];   // 16 KB, dbl-buffered h
    __shared__ float part[4][4][2][128];              // 16 KB, [grp][kh][row][gc]
    __shared__ __align__(8) u64 mbars[8];             // [buf*4+grp]

    cg::cluster_group cluster = cg::this_cluster();
    const int tid  = threadIdx.x;
    const int rank = (int)cluster.block_rank();
    const int cid  = blockIdx.x >> 3;
    const int b0   = cid * 8;

    // phase-1 roles (champion mapping)
    const int gcA = tid & 63;
    const int gcB = gcA + 64;
    const int kh  = tid >> 6;                 // k block [kh*64, kh*64+64)
    const int colA = (gcA >> 5) * 256 + rank * 32 + (gcA & 31);
    const int colB = (gcB >> 5) * 256 + rank * 32 + (gcB & 31);

    // epilogue roles: warp er owns batch row er
    const int er   = tid >> 5;                // 0..7
    const int ec   = tid & 31;
    const int egrp = er >> 1;                 // group 0..3
    const int erow = er & 1;                  // row within group

    // U slice in registers: 32 k-pairs x 2 columns
    u64 u2a[32], u2b[32];
#pragma unroll
    for (int kp = 0; kp < 32; kp++) {
        int k = kh * 64 + 2 * kp;
        u2a[kp] = pack2(U[(size_t)k * G4 + colA], U[(size_t)(k + 1) * G4 + colA]);
        u2b[kp] = pack2(U[(size_t)k * G4 + colB], U[(size_t)(k + 1) * G4 + colB]);
    }

    // init smem
    for (int i = tid; i < 2 * 8 * HID; i += 256) ((float*)hbuf)[i] = 0.f;
    const unsigned mbar0 = smem_u32(&mbars[0]);
    if (tid == 0) {
#pragma unroll
        for (int i = 0; i < 8; i++) mbar_init(mbar0 + 8u * i, 1);
    }

    // per-rank remote addresses
    const unsigned hloc = smem_u32(&hbuf[0][er][rank * 32 + ec]);
    unsigned rH[8], rM[8];
#pragma unroll
    for (int pr = 0; pr < 8; pr++) {
        rH[pr] = mapa_u32(hloc, pr);
        rM[pr] = mapa_u32(mbar0, pr);
    }

    cluster.sync();   // barriers + zeroed hbuf visible cluster-wide
    if (tid == 0) {
#pragma unroll
        for (int i = 0; i < 8; i++) mbar_expect_tx(mbar0 + 8u * i, 2048);
    }

    const float* xptr = xw + ((size_t)(b0 + er) * TLEN) * G4 + rank * 32 + ec;
    float* hptr = WRITE_SEQ
        ? out_seq + ((size_t)(b0 + er) * TLEN) * HID + rank * 32 + ec
        : nullptr;

    float c_state = 0.f;
    unsigned par = 0;   // parity bits, idx = p*4+g

    // preload xg for t=0 (double-buffered one step ahead from here on)
    float xg0 = xptr[0], xg1 = xptr[HID], xg2 = xptr[2 * HID], xg3 = xptr[3 * HID];
    xptr += G4;

    for (int t = 0; t < TLEN; t++) {
        const int p  = t & 1;
        const int nb = p ^ 1;
        const unsigned hoff = (unsigned)(nb * 8 * HID) * 4u;
        const unsigned moffG = (unsigned)(nb * 4 + egrp) * 8u;

        // prefetch xg for t+1 (full-step window: hides all DRAM jitter)
        float nx0 = 0.f, nx1 = 0.f, nx2 = 0.f, nx3 = 0.f;
        if (t + 1 < TLEN) {
            nx0 = xptr[0]; nx1 = xptr[HID]; nx2 = xptr[2 * HID]; nx3 = xptr[3 * HID];
            xptr += G4;
        }

#pragma unroll
        for (int g = 0; g < 4; g++) {
            // ---- wait for this buffer+group's h from all ranks ----
            if (t > 0) {
                const unsigned idx = (unsigned)(p * 4 + g);
                const unsigned mb  = mbar0 + idx * 8u;
                mbar_wait_cluster(mb, (par >> idx) & 1u);
                par ^= (1u << idx);
                if (tid == 0) mbar_expect_tx(mb, 2048);   // re-arm
            }

            // ---- phase 1 for this group's 2 rows ----
            u64 accA0 = 0ull, accA1 = 0ull, accB0 = 0ull, accB1 = 0ull;
#pragma unroll
            for (int kq = 0; kq < 16; kq++) {
                const int k = kh * 64 + kq * 4;
                float4 h40 = *(const float4*)&hbuf[p][2 * g][k];
                float4 h41 = *(const float4*)&hbuf[p][2 * g + 1][k];
                u64 ua0 = u2a[2 * kq], ua1 = u2a[2 * kq + 1];
                u64 ub0 = u2b[2 * kq], ub1 = u2b[2 * kq + 1];
                u64 h0lo = pack2(h40.x, h40.y), h0hi = pack2(h40.z, h40.w);
                u64 h1lo = pack2(h41.x, h41.y), h1hi = pack2(h41.z, h41.w);
                accA0 = ffma2(h0lo, ua0, accA0);
                accA0 = ffma2(h0hi, ua1, accA0);
                accA1 = ffma2(h1lo, ua0, accA1);
                accA1 = ffma2(h1hi, ua1, accA1);
                accB0 = ffma2(h0lo, ub0, accB0);
                accB0 = ffma2(h0hi, ub1, accB0);
                accB1 = ffma2(h1lo, ub0, accB1);
                accB1 = ffma2(h1hi, ub1, accB1);
            }
            part[g][kh][0][gcA] = f2lo(accA0) + f2hi(accA0);
            part[g][kh][1][gcA] = f2lo(accA1) + f2hi(accA1);
            part[g][kh][0][gcB] = f2lo(accB0) + f2hi(accB0);
            part[g][kh][1][gcB] = f2lo(accB1) + f2hi(accB1);

            // ---- warp-specialized barrier: producers arrive, consumers sync ----
            if (egrp != g) {
                named_bar_arrive(1 + g, 256);
                continue;      // straight into next group's wait + phase1
            }
            named_bar_sync(1 + g, 256);

            // ---- epilogue for this group (its 2 warps only) ----
            {
                float v0 = xg0, v1 = xg1, v2 = xg2, v3 = xg3;
#pragma unroll
                for (int q = 0; q < 4; q++) {
                    v0 += part[g][q][erow][ec];
                    v1 += part[g][q][erow][32 + ec];
                    v2 += part[g][q][erow][64 + ec];
                    v3 += part[g][q][erow][96 + ec];
                }
                float ig = sigm_f(v0);
                float fg = sigm_f(v1);
                float gg = tanh_f(v2);
                float og = sigm_f(v3);
                c_state = fg * c_state + ig * gg;
                float hnew = og * tanh_f(c_state);

                if (WRITE_SEQ) { *hptr = hnew; hptr += HID; }

                if (t < TLEN - 1) {
#pragma unroll
                    for (int pr = 0; pr < 8; pr++)
                        st_async_f32(rH[pr] + hoff, hnew, rM[pr] + moffG);
                } else if (!WRITE_SEQ) {
                    out_last[(size_t)(b0 + er) * HID + rank * 32 + ec] = hnew;
                }
            }
        }

        xg0 = nx0; xg1 = nx1; xg2 = nx2; xg3 = nx3;
    }

    cluster.sync();   // don't exit with peer-targeted async traffic in flight
}

// ---------------------------------------------------------------------------
// Dense head: out[b] = relu( relu(h_last[b] @ Wd1 + bd1) @ Wd2 + bd2 )
// ---------------------------------------------------------------------------
__global__ __launch_bounds__(128)
void dense_head_kernel(const float* __restrict__ hlast,
                       const float* __restrict__ Wd1, const float* __restrict__ bd1,
                       const float* __restrict__ Wd2, const float* __restrict__ bd2,
                       float* __restrict__ out)
{
    __shared__ float hs[HID];
    __shared__ float red[4];
    const int b = blockIdx.x;
    const int j = threadIdx.x;

    hs[j]       = hlast[b * HID + j];
    hs[j + 128] = hlast[b * HID + j + 128];
    __syncthreads();

    float acc = bd1[j];
#pragma unroll 8
    for (int k = 0; k < HID; k++) acc = fmaf(hs[k], Wd1[k * 128 + j], acc);
    float hm = fmaxf(acc, 0.f) * Wd2[j];

#pragma unroll
    for (int off = 16; off > 0; off >>= 1)
        hm += __shfl_down_sync(0xffffffffu, hm, off);
    if ((j & 31) == 0) red[j >> 5] = hm;
    __syncthreads();
    if (j == 0) {
        float s = red[0] + red[1] + red[2] + red[3] + bd2[0];
        out[b] = fmaxf(s, 0.f);
    }
}

// ---------------------------------------------------------------------------
extern "C" void kernel_launch(void* const* d_in, const int* in_sizes, int n_in,
                              void* d_out, int out_size)
{
    const float* x   = (const float*)d_in[0];
    const float* W1  = (const float*)d_in[1];
    const float* U1  = (const float*)d_in[2];
    const float* b1  = (const float*)d_in[3];
    const float* W2  = (const float*)d_in[4];
    const float* U2  = (const float*)d_in[5];
    const float* b2  = (const float*)d_in[6];
    const float* Wd1 = (const float*)d_in[7];
    const float* bd1 = (const float*)d_in[8];
    const float* Wd2 = (const float*)d_in[9];
    const float* bd2 = (const float*)d_in[10];
    float* out = (float*)d_out;

    float *xw, *hseq, *hlast;
    cudaGetSymbolAddress((void**)&xw, g_xw);
    cudaGetSymbolAddress((void**)&hseq, g_hseq);
    cudaGetSymbolAddress((void**)&hlast, g_hlast);

    dim3 ggrid(G4 / 128, (BATCH * TLEN) / 128);

    gemm_bias_kernel<<<ggrid, 256>>>(x, W1, b1, xw, 128);
    lstm_layer<true><<<128, 256>>>(xw, U1, hseq, nullptr);
    gemm_bias_kernel<<<ggrid, 256>>>(hseq, W2, b2, xw, 256);
    lstm_layer<false><<<128, 256>>>(xw, U2, nullptr, hlast);
    dense_head_kernel<<<BATCH, 128>>>(hlast, Wd1, bd1, Wd2, bd2, out);
}

// round 12
// speedup vs baseline: 1.3648x; 1.3648x over previous
#include <cuda_runtime.h>
#include <cuda_bf16.h>
#include <cooperative_groups.h>
#include <cstdint>
#include <cstddef>

namespace cg = cooperative_groups;
using u64 = unsigned long long;

#define BATCH 128
#define TLEN  1024
#define HID   256
#define G4    1024  // 4*HID

// ---------------- packed f32x2 helpers ----------------
__device__ __forceinline__ u64 ffma2(u64 a, u64 b, u64 c) {
    u64 d;
    asm("fma.rn.f32x2 %0, %1, %2, %3;" : "=l"(d) : "l"(a), "l"(b), "l"(c));
    return d;
}
__device__ __forceinline__ u64 pack2(float lo, float hi) {
    u64 r;
    asm("mov.b64 %0, {%1, %2};" : "=l"(r) : "f"(lo), "f"(hi));
    return r;
}
__device__ __forceinline__ float f2lo(u64 v) { return __uint_as_float((unsigned)(v & 0xffffffffull)); }
__device__ __forceinline__ float f2hi(u64 v) { return __uint_as_float((unsigned)(v >> 32)); }

__device__ __forceinline__ float sigm_f(float x) {
    x = fminf(fmaxf(x, -30.f), 30.f);
    return __fdividef(1.f, 1.f + __expf(-x));
}
__device__ __forceinline__ float tanh_f(float x) {
    x = fminf(fmaxf(x, -15.f), 15.f);
    float e = __expf(2.f * x);
    return __fdividef(e - 1.f, e + 1.f);
}

// ---------------- tf32 mma helpers ----------------
__device__ __forceinline__ unsigned cvt_tf32(float f) {
    unsigned r;
    asm("cvt.rna.tf32.f32 %0, %1;" : "=r"(r) : "f"(f));
    return r;
}
__device__ __forceinline__ void mma_tf32(float* d, const unsigned* a, const unsigned* b) {
    asm("mma.sync.aligned.m16n8k8.row.col.f32.tf32.tf32.f32 "
        "{%0,%1,%2,%3},{%4,%5,%6,%7},{%8,%9},{%0,%1,%2,%3};"
        : "+f"(d[0]), "+f"(d[1]), "+f"(d[2]), "+f"(d[3])
        : "r"(a[0]), "r"(a[1]), "r"(a[2]), "r"(a[3]), "r"(b[0]), "r"(b[1]));
}

// ---------------- cluster async-store primitives ----------------
__device__ __forceinline__ unsigned smem_u32(const void* p) {
    return (unsigned)__cvta_generic_to_shared(p);
}
__device__ __forceinline__ unsigned mapa_u32(unsigned laddr, unsigned rank) {
    unsigned r;
    asm("mapa.shared::cluster.u32 %0, %1, %2;" : "=r"(r) : "r"(laddr), "r"(rank));
    return r;
}
__device__ __forceinline__ void st_async_f32(unsigned raddr, float v, unsigned rmbar) {
    asm volatile("st.async.shared::cluster.mbarrier::complete_tx::bytes.b32 [%0], %1, [%2];"
                 :: "r"(raddr), "r"(__float_as_uint(v)), "r"(rmbar) : "memory");
}
__device__ __forceinline__ void mbar_init(unsigned mbar, unsigned cnt) {
    asm volatile("mbarrier.init.shared.b64 [%0], %1;" :: "r"(mbar), "r"(cnt) : "memory");
}
__device__ __forceinline__ void mbar_expect_tx(unsigned mbar, unsigned bytes) {
    asm volatile("mbarrier.arrive.expect_tx.shared.b64 _, [%0], %1;"
                 :: "r"(mbar), "r"(bytes) : "memory");
}
__device__ __forceinline__ void mbar_wait_cluster(unsigned mbar, unsigned parity) {
    asm volatile(
        "{\n\t"
        ".reg .pred P;\n"
        "LWAIT_%=:\n\t"
        "mbarrier.try_wait.parity.acquire.cluster.shared::cta.b64 P, [%0], %1, 0x989680;\n\t"
        "@P bra LDONE_%=;\n\t"
        "bra LWAIT_%=;\n"
        "LDONE_%=:\n\t"
        "}"
        :: "r"(mbar), "r"(parity) : "memory");
}

// ---------------- scratch (static device globals) ----------------
__device__ float g_xw[(size_t)BATCH * TLEN * G4];     // 512 MB, reused by both layers
__device__ float g_hseq[(size_t)BATCH * TLEN * HID];  // 128 MB
__device__ float g_hlast[BATCH * HID];

// ---------------------------------------------------------------------------
// tf32 GEMM: C[M,1024] = A[M,K] @ B[K,1024] + bias, M=131072, K in {128,256}
// 128x128 CTA tile, BK=32, 256 threads = 8 warps (2m x 4n), warp tile 64x32,
// m16n8k8 tf32 mma.sync, fp32 accumulate. cvt.rna.tf32 applied at smem fill.
// SMEM pads: As[128][36] (frag loads conflict-free: bank = 4g+tg),
//            Bs[32][136] (bank = 8tg+g). Both 16B-aligned rows.
// ---------------------------------------------------------------------------
__global__ __launch_bounds__(256, 2)
void gemm_tf32_bias(const float* __restrict__ A, const float* __restrict__ B,
                    const float* __restrict__ bias, float* __restrict__ C, int K)
{
    __shared__ unsigned As[128][36];
    __shared__ unsigned Bs[32][136];

    const int tid = threadIdx.x;
    const int n0  = blockIdx.x * 128;
    const size_t m0 = (size_t)blockIdx.y * 128;
    const int warp = tid >> 5, lane = tid & 31;
    const int wm = (warp >> 2) * 64;   // warp row offset (2 m-warps)
    const int wn = (warp & 3) * 32;    // warp col offset (4 n-warps)
    const int g  = lane >> 2;          // group id 0..7
    const int tg = lane & 3;           // thread-in-group 0..3

    float acc[4][4][4];
#pragma unroll
    for (int mf = 0; mf < 4; mf++)
#pragma unroll
        for (int nf = 0; nf < 4; nf++)
#pragma unroll
            for (int i = 0; i < 4; i++) acc[mf][nf][i] = 0.f;

    for (int kb = 0; kb < K; kb += 32) {
        // load + convert A tile: 128 rows x 32 k
#pragma unroll
        for (int i = 0; i < 4; i++) {
            int idx = tid + i * 256;
            int r = idx >> 3, c4 = (idx & 7) * 4;
            float4 v = *(const float4*)&A[(m0 + r) * K + kb + c4];
            uint4 t;
            t.x = cvt_tf32(v.x); t.y = cvt_tf32(v.y);
            t.z = cvt_tf32(v.z); t.w = cvt_tf32(v.w);
            *(uint4*)&As[r][c4] = t;
        }
        // load + convert B tile: 32 k x 128 n
#pragma unroll
        for (int i = 0; i < 4; i++) {
            int idx = tid + i * 256;
            int r = idx >> 5, c4 = (idx & 31) * 4;
            float4 v = *(const float4*)&B[(size_t)(kb + r) * G4 + n0 + c4];
            uint4 t;
            t.x = cvt_tf32(v.x); t.y = cvt_tf32(v.y);
            t.z = cvt_tf32(v.z); t.w = cvt_tf32(v.w);
            *(uint4*)&Bs[r][c4] = t;
        }
        __syncthreads();

#pragma unroll
        for (int ks = 0; ks < 4; ks++) {
            const int k0 = ks * 8;
            unsigned af[4][4], bf[4][2];
#pragma unroll
            for (int mf = 0; mf < 4; mf++) {
                int row = wm + mf * 16;
                af[mf][0] = As[row + g][k0 + tg];
                af[mf][1] = As[row + g + 8][k0 + tg];
                af[mf][2] = As[row + g][k0 + tg + 4];
                af[mf][3] = As[row + g + 8][k0 + tg + 4];
            }
#pragma unroll
            for (int nf = 0; nf < 4; nf++) {
                int col = wn + nf * 8;
                bf[nf][0] = Bs[k0 + tg][col + g];
                bf[nf][1] = Bs[k0 + tg + 4][col + g];
            }
#pragma unroll
            for (int mf = 0; mf < 4; mf++)
#pragma unroll
                for (int nf = 0; nf < 4; nf++)
                    mma_tf32(acc[mf][nf], af[mf], bf[nf]);
        }
        __syncthreads();
    }

    // epilogue: add bias, store
#pragma unroll
    for (int nf = 0; nf < 4; nf++) {
        int col = n0 + wn + nf * 8 + 2 * tg;
        float b0 = bias[col], b1 = bias[col + 1];
#pragma unroll
        for (int mf = 0; mf < 4; mf++) {
            size_t row = m0 + wm + mf * 16 + g;
            float2 v0 = {acc[mf][nf][0] + b0, acc[mf][nf][1] + b1};
            float2 v1 = {acc[mf][nf][2] + b0, acc[mf][nf][3] + b1};
            *(float2*)&C[row * G4 + col] = v0;
            *(float2*)&C[(row + 8) * G4 + col] = v1;
        }
    }
}

// ---------------------------------------------------------------------------
// Persistent-cluster LSTM recurrence (R7 CHAMPION — unchanged).
// Two-group pipeline, st.async exchange, 256 threads, 16 clusters x 8 CTAs.
// ---------------------------------------------------------------------------
template <bool WRITE_SEQ>
__global__ void __cluster_dims__(8, 1, 1) __launch_bounds__(256, 1)
lstm_layer(const float* __restrict__ xw, const float* __restrict__ U,
           float* __restrict__ out_seq, float* __restrict__ out_last)
{
    __shared__ __align__(16) float hbuf[2][8][HID];   // 16 KB, dbl-buffered h
    __shared__ float part[2][4][4][128];              // 16 KB, [grp][kh][row][gc]
    __shared__ __align__(8) u64 mbars[4];             // [buf*2+grp]

    cg::cluster_group cluster = cg::this_cluster();
    const int tid  = threadIdx.x;
    const int rank = (int)cluster.block_rank();
    const int cid  = blockIdx.x >> 3;
    const int b0   = cid * 8;

    // phase-1 roles
    const int gcA = tid & 63;
    const int gcB = gcA + 64;
    const int kh  = tid >> 6;                 // k block [kh*64, kh*64+64)
    const int colA = (gcA >> 5) * 256 + rank * 32 + (gcA & 31);
    const int colB = (gcB >> 5) * 256 + rank * 32 + (gcB & 31);

    // epilogue roles
    const int er   = tid >> 5;                // batch row within cluster (0..7)
    const int ec   = tid & 31;                // h column within rank's 32
    const int egrp = er >> 2;                 // this thread's epilogue group
    const int erow = er & 3;                  // row within group

    // U slice in registers: 32 k-pairs x 2 columns
    u64 u2a[32], u2b[32];
#pragma unroll
    for (int kp = 0; kp < 32; kp++) {
        int k = kh * 64 + 2 * kp;
        u2a[kp] = pack2(U[(size_t)k * G4 + colA], U[(size_t)(k + 1) * G4 + colA]);
        u2b[kp] = pack2(U[(size_t)k * G4 + colB], U[(size_t)(k + 1) * G4 + colB]);
    }

    // init smem
    for (int i = tid; i < 2 * 8 * HID; i += 256) ((float*)hbuf)[i] = 0.f;
    const unsigned mbar0 = smem_u32(&mbars[0]);
    if (tid == 0) {
#pragma unroll
        for (int i = 0; i < 4; i++) mbar_init(mbar0 + 8u * i, 1);
    }

    // per-rank remote addresses
    const unsigned hloc = smem_u32(&hbuf[0][er][rank * 32 + ec]);
    unsigned rH[8], rM[8];
#pragma unroll
    for (int pr = 0; pr < 8; pr++) {
        rH[pr] = mapa_u32(hloc, pr);
        rM[pr] = mapa_u32(mbar0, pr);
    }

    cluster.sync();   // barriers + zeroed hbuf visible cluster-wide
    if (tid == 0) {
#pragma unroll
        for (int i = 0; i < 4; i++) mbar_expect_tx(mbar0 + 8u * i, 4096);
    }

    const float* xptr = xw + ((size_t)(b0 + er) * TLEN) * G4 + rank * 32 + ec;
    float* hptr = WRITE_SEQ
        ? out_seq + ((size_t)(b0 + er) * TLEN) * HID + rank * 32 + ec
        : nullptr;

    float c_state = 0.f;
    unsigned pp00 = 0, pp01 = 0, pp10 = 0, pp11 = 0;  // parity[buf][grp]

    for (int t = 0; t < TLEN; t++) {
        const int p  = t & 1;
        const int nb = p ^ 1;
        const unsigned hoff = (unsigned)(nb * 8 * HID) * 4u;
        const unsigned moffG = (unsigned)(nb * 2 + egrp) * 8u;

        // prefetch own row's xw gate inputs (consumed in own group's epilogue)
        float xg0 = xptr[0];
        float xg1 = xptr[HID];
        float xg2 = xptr[2 * HID];
        float xg3 = xptr[3 * HID];
        xptr += G4;

#pragma unroll
        for (int g = 0; g < 2; g++) {
            // ---- wait for this buffer+group's h from all ranks ----
            if (t > 0) {
                const unsigned mb = mbar0 + (unsigned)(p * 2 + g) * 8u;
                if (p == 0) {
                    if (g == 0) { mbar_wait_cluster(mb, pp00); pp00 ^= 1; }
                    else        { mbar_wait_cluster(mb, pp01); pp01 ^= 1; }
                } else {
                    if (g == 0) { mbar_wait_cluster(mb, pp10); pp10 ^= 1; }
                    else        { mbar_wait_cluster(mb, pp11); pp11 ^= 1; }
                }
                if (tid == 0) mbar_expect_tx(mb, 4096);   // re-arm
            }

            // ---- phase 1 for this group's 4 rows ----
            u64 accA[4], accB[4];
#pragma unroll
            for (int r = 0; r < 4; r++) { accA[r] = 0ull; accB[r] = 0ull; }

#pragma unroll
            for (int kq = 0; kq < 16; kq++) {
                const int k = kh * 64 + kq * 4;
                float4 h4[4];
#pragma unroll
                for (int r = 0; r < 4; r++)
                    h4[r] = *(const float4*)&hbuf[p][g * 4 + r][k];
                u64 ua0 = u2a[2 * kq], ua1 = u2a[2 * kq + 1];
                u64 ub0 = u2b[2 * kq], ub1 = u2b[2 * kq + 1];
#pragma unroll
                for (int r = 0; r < 4; r++) {
                    u64 hlo = pack2(h4[r].x, h4[r].y);
                    u64 hhi = pack2(h4[r].z, h4[r].w);
                    accA[r] = ffma2(hlo, ua0, accA[r]);
                    accA[r] = ffma2(hhi, ua1, accA[r]);
                    accB[r] = ffma2(hlo, ub0, accB[r]);
                    accB[r] = ffma2(hhi, ub1, accB[r]);
                }
            }
#pragma unroll
            for (int r = 0; r < 4; r++) {
                part[g][kh][r][gcA] = f2lo(accA[r]) + f2hi(accA[r]);
                part[g][kh][r][gcB] = f2lo(accB[r]) + f2hi(accB[r]);
            }
            __syncthreads();

            // ---- epilogue for this group (warps whose rows belong to it) ----
            if (egrp == g) {
                float v0 = xg0, v1 = xg1, v2 = xg2, v3 = xg3;
#pragma unroll
                for (int q = 0; q < 4; q++) {
                    v0 += part[g][q][erow][ec];
                    v1 += part[g][q][erow][32 + ec];
                    v2 += part[g][q][erow][64 + ec];
                    v3 += part[g][q][erow][96 + ec];
                }
                float ig = sigm_f(v0);
                float fg = sigm_f(v1);
                float gg = tanh_f(v2);
                float og = sigm_f(v3);
                c_state = fg * c_state + ig * gg;
                float hnew = og * tanh_f(c_state);

                if (WRITE_SEQ) { *hptr = hnew; hptr += HID; }

                if (t < TLEN - 1) {
#pragma unroll
                    for (int pr = 0; pr < 8; pr++)
                        st_async_f32(rH[pr] + hoff, hnew, rM[pr] + moffG);
                } else if (!WRITE_SEQ) {
                    out_last[(size_t)(b0 + er) * HID + rank * 32 + ec] = hnew;
                }
            }
        }
    }

    cluster.sync();   // don't exit with peer-targeted async traffic in flight
}

// ---------------------------------------------------------------------------
// Dense head: out[b] = relu( relu(h_last[b] @ Wd1 + bd1) @ Wd2 + bd2 )
// ---------------------------------------------------------------------------
__global__ __launch_bounds__(128)
void dense_head_kernel(const float* __restrict__ hlast,
                       const float* __restrict__ Wd1, const float* __restrict__ bd1,
                       const float* __restrict__ Wd2, const float* __restrict__ bd2,
                       float* __restrict__ out)
{
    __shared__ float hs[HID];
    __shared__ float red[4];
    const int b = blockIdx.x;
    const int j = threadIdx.x;

    hs[j]       = hlast[b * HID + j];
    hs[j + 128] = hlast[b * HID + j + 128];
    __syncthreads();

    float acc = bd1[j];
#pragma unroll 8
    for (int k = 0; k < HID; k++) acc = fmaf(hs[k], Wd1[k * 128 + j], acc);
    float hm = fmaxf(acc, 0.f) * Wd2[j];

#pragma unroll
    for (int off = 16; off > 0; off >>= 1)
        hm += __shfl_down_sync(0xffffffffu, hm, off);
    if ((j & 31) == 0) red[j >> 5] = hm;
    __syncthreads();
    if (j == 0) {
        float s = red[0] + red[1] + red[2] + red[3] + bd2[0];
        out[b] = fmaxf(s, 0.f);
    }
}

// ---------------------------------------------------------------------------
extern "C" void kernel_launch(void* const* d_in, const int* in_sizes, int n_in,
                              void* d_out, int out_size)
{
    const float* x   = (const float*)d_in[0];
    const float* W1  = (const float*)d_in[1];
    const float* U1  = (const float*)d_in[2];
    const float* b1  = (const float*)d_in[3];
    const float* W2  = (const float*)d_in[4];
    const float* U2  = (const float*)d_in[5];
    const float* b2  = (const float*)d_in[6];
    const float* Wd1 = (const float*)d_in[7];
    const float* bd1 = (const float*)d_in[8];
    const float* Wd2 = (const float*)d_in[9];
    const float* bd2 = (const float*)d_in[10];
    float* out = (float*)d_out;

    float *xw, *hseq, *hlast;
    cudaGetSymbolAddress((void**)&xw, g_xw);
    cudaGetSymbolAddress((void**)&hseq, g_hseq);
    cudaGetSymbolAddress((void**)&hlast, g_hlast);

    dim3 ggrid(G4 / 128, (BATCH * TLEN) / 128);

    gemm_tf32_bias<<<ggrid, 256>>>(x, W1, b1, xw, 128);
    lstm_layer<true><<<128, 256>>>(xw, U1, hseq, nullptr);
    gemm_tf32_bias<<<ggrid, 256>>>(hseq, W2, b2, xw, 256);
    lstm_layer<false><<<128, 256>>>(xw, U2, nullptr, hlast);
    dense_head_kernel<<<BATCH, 128>>>(hlast, Wd1, bd1, Wd2, bd2, out);
}